// round 6
// baseline (speedup 1.0000x reference)
#include <cuda_runtime.h>
#include <math.h>

#define BB  2
#define LL  2048
#define DD  1024
#define HH  16
#define DKK 64

// Scratch (allocation-free): Q/K/V in [B,H,L,DK], attention out in [B,L,D]
__device__ float g_Q[BB*HH*LL*DKK];
__device__ float g_K[BB*HH*LL*DKK];
__device__ float g_V[BB*HH*LL*DKK];
__device__ float g_Ao[BB*LL*DD];

// ---------------------------------------------------------------------------
// C = A[4096,1024] @ W[1024,1024]^T + bias. Double-buffered smem, BK=16,
// 128x128 tile, 8x8 per thread, 256 threads.
// MODE 0: row-major store. MODE 1: scatter to [B,H,L,DK] head layout.
// ---------------------------------------------------------------------------
template<int MODE>
__global__ __launch_bounds__(256)
void gemm_kernel(const float* __restrict__ A, const float* __restrict__ W,
                 const float* __restrict__ bias, float* __restrict__ C)
{
    constexpr int KD = 1024;
    constexpr int N  = 1024;
    __shared__ float As[2][16][128];
    __shared__ float Bs[2][16][128];

    const int tid = threadIdx.x;
    const int bm  = blockIdx.y * 128;
    const int bn  = blockIdx.x * 128;
    const int lr  = tid >> 2;          // 0..63
    const int lc  = (tid & 3) << 2;    // 0,4,8,12
    const int tx  = tid & 15;
    const int ty  = tid >> 4;

    float acc[8][8];
#pragma unroll
    for (int i = 0; i < 8; i++)
#pragma unroll
        for (int j = 0; j < 8; j++) acc[i][j] = 0.f;

    const float* Ap = A + (size_t)bm * KD;
    const float* Wp = W + (size_t)bn * KD;

    // preload tile 0
    {
        float4 a0 = *(const float4*)(Ap + (size_t)lr * KD + lc);
        float4 a1 = *(const float4*)(Ap + (size_t)(lr + 64) * KD + lc);
        float4 w0 = *(const float4*)(Wp + (size_t)lr * KD + lc);
        float4 w1 = *(const float4*)(Wp + (size_t)(lr + 64) * KD + lc);
        As[0][lc+0][lr]    = a0.x; As[0][lc+1][lr]    = a0.y; As[0][lc+2][lr]    = a0.z; As[0][lc+3][lr]    = a0.w;
        As[0][lc+0][lr+64] = a1.x; As[0][lc+1][lr+64] = a1.y; As[0][lc+2][lr+64] = a1.z; As[0][lc+3][lr+64] = a1.w;
        Bs[0][lc+0][lr]    = w0.x; Bs[0][lc+1][lr]    = w0.y; Bs[0][lc+2][lr]    = w0.z; Bs[0][lc+3][lr]    = w0.w;
        Bs[0][lc+0][lr+64] = w1.x; Bs[0][lc+1][lr+64] = w1.y; Bs[0][lc+2][lr+64] = w1.z; Bs[0][lc+3][lr+64] = w1.w;
    }
    __syncthreads();

    int sb = 0;
    for (int k0 = 0; k0 < KD; k0 += 16) {
        const int nxt = k0 + 16;
        float4 a0, a1, w0, w1;
        if (nxt < KD) {
            a0 = *(const float4*)(Ap + (size_t)lr * KD + nxt + lc);
            a1 = *(const float4*)(Ap + (size_t)(lr + 64) * KD + nxt + lc);
            w0 = *(const float4*)(Wp + (size_t)lr * KD + nxt + lc);
            w1 = *(const float4*)(Wp + (size_t)(lr + 64) * KD + nxt + lc);
        }
#pragma unroll
        for (int kk = 0; kk < 16; kk++) {
            float ra[8], rb[8];
            *(float4*)&ra[0] = *(const float4*)&As[sb][kk][ty*8];
            *(float4*)&ra[4] = *(const float4*)&As[sb][kk][ty*8+4];
            *(float4*)&rb[0] = *(const float4*)&Bs[sb][kk][tx*8];
            *(float4*)&rb[4] = *(const float4*)&Bs[sb][kk][tx*8+4];
#pragma unroll
            for (int i = 0; i < 8; i++)
#pragma unroll
                for (int j = 0; j < 8; j++)
                    acc[i][j] = fmaf(ra[i], rb[j], acc[i][j]);
        }
        if (nxt < KD) {
            const int nb = sb ^ 1;
            As[nb][lc+0][lr]    = a0.x; As[nb][lc+1][lr]    = a0.y; As[nb][lc+2][lr]    = a0.z; As[nb][lc+3][lr]    = a0.w;
            As[nb][lc+0][lr+64] = a1.x; As[nb][lc+1][lr+64] = a1.y; As[nb][lc+2][lr+64] = a1.z; As[nb][lc+3][lr+64] = a1.w;
            Bs[nb][lc+0][lr]    = w0.x; Bs[nb][lc+1][lr]    = w0.y; Bs[nb][lc+2][lr]    = w0.z; Bs[nb][lc+3][lr]    = w0.w;
            Bs[nb][lc+0][lr+64] = w1.x; Bs[nb][lc+1][lr+64] = w1.y; Bs[nb][lc+2][lr+64] = w1.z; Bs[nb][lc+3][lr+64] = w1.w;
            __syncthreads();
            sb = nb;
        }
    }

    float bv[8];
#pragma unroll
    for (int j = 0; j < 8; j++) bv[j] = bias[bn + tx*8 + j];

#pragma unroll
    for (int i = 0; i < 8; i++) {
        int m  = bm + ty*8 + i;
        int n0 = bn + tx*8;
#pragma unroll
        for (int v = 0; v < 2; v++) {
            float4 o;
            o.x = acc[i][v*4+0] + bv[v*4+0];
            o.y = acc[i][v*4+1] + bv[v*4+1];
            o.z = acc[i][v*4+2] + bv[v*4+2];
            o.w = acc[i][v*4+3] + bv[v*4+3];
            int n = n0 + v*4;
            if (MODE == 0) {
                *(float4*)(C + (size_t)m * N + n) = o;
            } else {
                int b = m >> 11;
                int l = m & 2047;
                int h = n >> 6;
                int dk = n & 63;
                *(float4*)(C + ((((size_t)b*HH + h)*LL + l)*DKK) + dk) = o;
            }
        }
    }
}

// ---------------------------------------------------------------------------
// Causal flash attention, fp32, vectorized-smem version.
// One block = 64 queries of one (b,h). BQ=BKV=64, DK=64, 256 threads.
// Layouts: Qt[d][r], Kt[d][c] (transposed), Vs[k][c], Pt[k][r] (transposed).
// All mainloop smem reads are LDS.128. Softmax entirely in registers via
// 16-lane shfl reductions; m/l state register-resident (replicated per row).
// smem = 4 * 64 * 68 * 4B = 69632 B (dynamic).
// ---------------------------------------------------------------------------
#define APAD 68

__global__ __launch_bounds__(256)
void attn_kernel(const float* __restrict__ Qg, const float* __restrict__ Kg,
                 const float* __restrict__ Vg, float* __restrict__ Og)
{
    extern __shared__ float smbuf[];
    float (*Qt)[APAD] = (float(*)[APAD])(smbuf);
    float (*Kt)[APAD] = (float(*)[APAD])(smbuf + 64*APAD);
    float (*Vs)[APAD] = (float(*)[APAD])(smbuf + 2*64*APAD);
    float (*Pt)[APAD] = (float(*)[APAD])(smbuf + 3*64*APAD);

    const int tid = threadIdx.x;
    const int qt = gridDim.x - 1 - blockIdx.x;   // big tiles first
    const int h = blockIdx.y, b = blockIdx.z;
    const size_t base = ((size_t)b*HH + h) * LL * DKK;
    const float* Qp = Qg + base + (size_t)qt * 64 * DKK;
    const float* Kp = Kg + base;
    const float* Vp = Vg + base;

    // loader mapping: lane-major over rows -> conflict-free transpose STS
    const int lr = tid & 63;     // tile row (k or q index)
    const int dg = tid >> 6;     // d-group 0..3 (16 floats each)

    // Load Q tile transposed: Qt[d][r]
    {
        const float* src = Qp + lr*DKK + dg*16;
#pragma unroll
        for (int jj = 0; jj < 4; jj++) {
            float4 v = *(const float4*)(src + jj*4);
            int d = dg*16 + jj*4;
            Qt[d+0][lr] = v.x; Qt[d+1][lr] = v.y; Qt[d+2][lr] = v.z; Qt[d+3][lr] = v.w;
        }
    }

    const int tr = tid >> 4, tc = tid & 15;
    const int r0 = tr * 4, c0 = tc * 4;

    float O[4][4];
    float m_st[4], l_st[4];
#pragma unroll
    for (int i = 0; i < 4; i++) {
        m_st[i] = -1e30f; l_st[i] = 0.f;
#pragma unroll
        for (int j = 0; j < 4; j++) O[i][j] = 0.f;
    }

    const int q_lo = qt * 64;
    const float scale = 0.125f;   // 1/sqrt(64)

    for (int kt = 0; kt <= qt; kt++) {
        const float* Kpt = Kp + (size_t)kt * 64 * DKK;
        const float* Vpt = Vp + (size_t)kt * 64 * DKK;

        // prefetch K/V into regs (8 independent LDG.128 chains)
        float4 kr[4], vr[4];
        {
            const float* ks = Kpt + lr*DKK + dg*16;
            const float* vs = Vpt + lr*DKK + dg*16;
#pragma unroll
            for (int jj = 0; jj < 4; jj++) { kr[jj] = *(const float4*)(ks + jj*4); }
#pragma unroll
            for (int jj = 0; jj < 4; jj++) { vr[jj] = *(const float4*)(vs + jj*4); }
        }
        __syncthreads();   // prior iteration's PV reads done before overwrite
#pragma unroll
        for (int jj = 0; jj < 4; jj++) {
            int d = dg*16 + jj*4;
            Kt[d+0][lr] = kr[jj].x; Kt[d+1][lr] = kr[jj].y;
            Kt[d+2][lr] = kr[jj].z; Kt[d+3][lr] = kr[jj].w;
            *(float4*)&Vs[lr][dg*16 + jj*4] = vr[jj];
        }
        __syncthreads();

        // ---- S = Q K^T : 2 LDS.128 per 16 FMA ----
        float s[4][4];
#pragma unroll
        for (int i = 0; i < 4; i++)
#pragma unroll
            for (int j = 0; j < 4; j++) s[i][j] = 0.f;
#pragma unroll 4
        for (int d = 0; d < 64; d++) {
            float4 qa = *(const float4*)&Qt[d][r0];
            float4 ka = *(const float4*)&Kt[d][c0];
            s[0][0] = fmaf(qa.x, ka.x, s[0][0]); s[0][1] = fmaf(qa.x, ka.y, s[0][1]);
            s[0][2] = fmaf(qa.x, ka.z, s[0][2]); s[0][3] = fmaf(qa.x, ka.w, s[0][3]);
            s[1][0] = fmaf(qa.y, ka.x, s[1][0]); s[1][1] = fmaf(qa.y, ka.y, s[1][1]);
            s[1][2] = fmaf(qa.y, ka.z, s[1][2]); s[1][3] = fmaf(qa.y, ka.w, s[1][3]);
            s[2][0] = fmaf(qa.z, ka.x, s[2][0]); s[2][1] = fmaf(qa.z, ka.y, s[2][1]);
            s[2][2] = fmaf(qa.z, ka.z, s[2][2]); s[2][3] = fmaf(qa.z, ka.w, s[2][3]);
            s[3][0] = fmaf(qa.w, ka.x, s[3][0]); s[3][1] = fmaf(qa.w, ka.y, s[3][1]);
            s[3][2] = fmaf(qa.w, ka.z, s[3][2]); s[3][3] = fmaf(qa.w, ka.w, s[3][3]);
        }

        // scale (+ mask only on diagonal tile)
        if (kt == qt) {
#pragma unroll
            for (int i = 0; i < 4; i++) {
                int qi = r0 + i;         // local; ki local = c0+j
#pragma unroll
                for (int j = 0; j < 4; j++)
                    s[i][j] = (c0 + j <= qi) ? s[i][j]*scale : -1e30f;
            }
        } else {
#pragma unroll
            for (int i = 0; i < 4; i++)
#pragma unroll
                for (int j = 0; j < 4; j++) s[i][j] *= scale;
        }

        // ---- online softmax in registers (16-lane shfl over tc) ----
#pragma unroll
        for (int i = 0; i < 4; i++) {
            float mx = fmaxf(fmaxf(s[i][0], s[i][1]), fmaxf(s[i][2], s[i][3]));
            mx = fmaxf(mx, __shfl_xor_sync(0xffffffffu, mx, 1));
            mx = fmaxf(mx, __shfl_xor_sync(0xffffffffu, mx, 2));
            mx = fmaxf(mx, __shfl_xor_sync(0xffffffffu, mx, 4));
            mx = fmaxf(mx, __shfl_xor_sync(0xffffffffu, mx, 8));
            float mn = fmaxf(m_st[i], mx);
            float corr = __expf(m_st[i] - mn);
            m_st[i] = mn;
            float rs = 0.f;
#pragma unroll
            for (int j = 0; j < 4; j++) {
                s[i][j] = __expf(s[i][j] - mn);
                rs += s[i][j];
            }
            rs += __shfl_xor_sync(0xffffffffu, rs, 1);
            rs += __shfl_xor_sync(0xffffffffu, rs, 2);
            rs += __shfl_xor_sync(0xffffffffu, rs, 4);
            rs += __shfl_xor_sync(0xffffffffu, rs, 8);
            l_st[i] = l_st[i]*corr + rs;
#pragma unroll
            for (int j = 0; j < 4; j++) O[i][j] *= corr;
        }

        // write P transposed: Pt[k][r]
#pragma unroll
        for (int i = 0; i < 4; i++)
#pragma unroll
            for (int j = 0; j < 4; j++)
                Pt[c0+j][r0+i] = s[i][j];
        __syncthreads();

        // ---- O += P V : 2 LDS.128 per 16 FMA ----
#pragma unroll 4
        for (int k = 0; k < 64; k++) {
            float4 pv = *(const float4*)&Pt[k][r0];
            float4 vv = *(const float4*)&Vs[k][c0];
            O[0][0] = fmaf(pv.x, vv.x, O[0][0]); O[0][1] = fmaf(pv.x, vv.y, O[0][1]);
            O[0][2] = fmaf(pv.x, vv.z, O[0][2]); O[0][3] = fmaf(pv.x, vv.w, O[0][3]);
            O[1][0] = fmaf(pv.y, vv.x, O[1][0]); O[1][1] = fmaf(pv.y, vv.y, O[1][1]);
            O[1][2] = fmaf(pv.y, vv.z, O[1][2]); O[1][3] = fmaf(pv.y, vv.w, O[1][3]);
            O[2][0] = fmaf(pv.z, vv.x, O[2][0]); O[2][1] = fmaf(pv.z, vv.y, O[2][1]);
            O[2][2] = fmaf(pv.z, vv.z, O[2][2]); O[2][3] = fmaf(pv.z, vv.w, O[2][3]);
            O[3][0] = fmaf(pv.w, vv.x, O[3][0]); O[3][1] = fmaf(pv.w, vv.y, O[3][1]);
            O[3][2] = fmaf(pv.w, vv.z, O[3][2]); O[3][3] = fmaf(pv.w, vv.w, O[3][3]);
        }
    }

    // normalize + store merged-head [B, L, D]
#pragma unroll
    for (int i = 0; i < 4; i++) {
        float inv = 1.f / l_st[i];
        int q = q_lo + r0 + i;
        float4 o = make_float4(O[i][0]*inv, O[i][1]*inv, O[i][2]*inv, O[i][3]*inv);
        *(float4*)(Og + ((size_t)b*LL + q)*DD + h*DKK + c0) = o;
    }
}

// ---------------------------------------------------------------------------
extern "C" void kernel_launch(void* const* d_in, const int* in_sizes, int n_in,
                              void* d_out, int out_size)
{
    const float* query = (const float*)d_in[0];
    const float* key   = (const float*)d_in[1];
    const float* value = (const float*)d_in[2];
    // d_in[3] = mask: exactly triu(ones,k=1) causal -> applied analytically
    const float* Wq = (const float*)d_in[4];
    const float* bq = (const float*)d_in[5];
    const float* Wk = (const float*)d_in[6];
    const float* bk = (const float*)d_in[7];
    const float* Wv = (const float*)d_in[8];
    const float* bv = (const float*)d_in[9];
    const float* Wo = (const float*)d_in[10];
    const float* bo = (const float*)d_in[11];
    float* out = (float*)d_out;

    float *gQ, *gK, *gV, *gAo;
    cudaGetSymbolAddress((void**)&gQ,  g_Q);
    cudaGetSymbolAddress((void**)&gK,  g_K);
    cudaGetSymbolAddress((void**)&gV,  g_V);
    cudaGetSymbolAddress((void**)&gAo, g_Ao);

    const int smem_attn = 4*64*APAD*(int)sizeof(float);   // 69632 B
    cudaFuncSetAttribute(attn_kernel, cudaFuncAttributeMaxDynamicSharedMemorySize,
                         smem_attn);

    dim3 ggrid(8, 32);   // N/128, M/128
    gemm_kernel<1><<<ggrid, 256>>>(query, Wq, bq, gQ);
    gemm_kernel<1><<<ggrid, 256>>>(key,   Wk, bk, gK);
    gemm_kernel<1><<<ggrid, 256>>>(value, Wv, bv, gV);
    attn_kernel<<<dim3(LL/64, HH, BB), 256, smem_attn>>>(gQ, gK, gV, gAo);
    gemm_kernel<0><<<ggrid, 256>>>(gAo, Wo, bo, out);
}

// round 7
// speedup vs baseline: 1.0060x; 1.0060x over previous
#include <cuda_runtime.h>
#include <math.h>

#define BB  2
#define LL  2048
#define DD  1024
#define HH  16
#define DKK 64

// Scratch (allocation-free): Q/K/V in [B,H,L,DK], attention out in [B,L,D]
__device__ float g_Q[BB*HH*LL*DKK];
__device__ float g_K[BB*HH*LL*DKK];
__device__ float g_V[BB*HH*LL*DKK];
__device__ float g_Ao[BB*LL*DD];

// ---------------------------------------------------------------------------
// C = A[4096,1024] @ W[1024,1024]^T + bias. Double-buffered smem, BK=16,
// 128x128 tile, 8x8 per thread, 256 threads.
// MODE 0: row-major store. MODE 1: scatter to [B,H,L,DK] head layout.
// ---------------------------------------------------------------------------
template<int MODE>
__global__ __launch_bounds__(256)
void gemm_kernel(const float* __restrict__ A, const float* __restrict__ W,
                 const float* __restrict__ bias, float* __restrict__ C)
{
    constexpr int KD = 1024;
    constexpr int N  = 1024;
    __shared__ float As[2][16][128];
    __shared__ float Bs[2][16][128];

    const int tid = threadIdx.x;
    const int bm  = blockIdx.y * 128;
    const int bn  = blockIdx.x * 128;
    const int lr  = tid >> 2;          // 0..63
    const int lc  = (tid & 3) << 2;    // 0,4,8,12
    const int tx  = tid & 15;
    const int ty  = tid >> 4;

    float acc[8][8];
#pragma unroll
    for (int i = 0; i < 8; i++)
#pragma unroll
        for (int j = 0; j < 8; j++) acc[i][j] = 0.f;

    const float* Ap = A + (size_t)bm * KD;
    const float* Wp = W + (size_t)bn * KD;

    // preload tile 0
    {
        float4 a0 = *(const float4*)(Ap + (size_t)lr * KD + lc);
        float4 a1 = *(const float4*)(Ap + (size_t)(lr + 64) * KD + lc);
        float4 w0 = *(const float4*)(Wp + (size_t)lr * KD + lc);
        float4 w1 = *(const float4*)(Wp + (size_t)(lr + 64) * KD + lc);
        As[0][lc+0][lr]    = a0.x; As[0][lc+1][lr]    = a0.y; As[0][lc+2][lr]    = a0.z; As[0][lc+3][lr]    = a0.w;
        As[0][lc+0][lr+64] = a1.x; As[0][lc+1][lr+64] = a1.y; As[0][lc+2][lr+64] = a1.z; As[0][lc+3][lr+64] = a1.w;
        Bs[0][lc+0][lr]    = w0.x; Bs[0][lc+1][lr]    = w0.y; Bs[0][lc+2][lr]    = w0.z; Bs[0][lc+3][lr]    = w0.w;
        Bs[0][lc+0][lr+64] = w1.x; Bs[0][lc+1][lr+64] = w1.y; Bs[0][lc+2][lr+64] = w1.z; Bs[0][lc+3][lr+64] = w1.w;
    }
    __syncthreads();

    int sb = 0;
    for (int k0 = 0; k0 < KD; k0 += 16) {
        const int nxt = k0 + 16;
        float4 a0, a1, w0, w1;
        if (nxt < KD) {
            a0 = *(const float4*)(Ap + (size_t)lr * KD + nxt + lc);
            a1 = *(const float4*)(Ap + (size_t)(lr + 64) * KD + nxt + lc);
            w0 = *(const float4*)(Wp + (size_t)lr * KD + nxt + lc);
            w1 = *(const float4*)(Wp + (size_t)(lr + 64) * KD + nxt + lc);
        }
#pragma unroll
        for (int kk = 0; kk < 16; kk++) {
            float ra[8], rb[8];
            *(float4*)&ra[0] = *(const float4*)&As[sb][kk][ty*8];
            *(float4*)&ra[4] = *(const float4*)&As[sb][kk][ty*8+4];
            *(float4*)&rb[0] = *(const float4*)&Bs[sb][kk][tx*8];
            *(float4*)&rb[4] = *(const float4*)&Bs[sb][kk][tx*8+4];
#pragma unroll
            for (int i = 0; i < 8; i++)
#pragma unroll
                for (int j = 0; j < 8; j++)
                    acc[i][j] = fmaf(ra[i], rb[j], acc[i][j]);
        }
        if (nxt < KD) {
            const int nb = sb ^ 1;
            As[nb][lc+0][lr]    = a0.x; As[nb][lc+1][lr]    = a0.y; As[nb][lc+2][lr]    = a0.z; As[nb][lc+3][lr]    = a0.w;
            As[nb][lc+0][lr+64] = a1.x; As[nb][lc+1][lr+64] = a1.y; As[nb][lc+2][lr+64] = a1.z; As[nb][lc+3][lr+64] = a1.w;
            Bs[nb][lc+0][lr]    = w0.x; Bs[nb][lc+1][lr]    = w0.y; Bs[nb][lc+2][lr]    = w0.z; Bs[nb][lc+3][lr]    = w0.w;
            Bs[nb][lc+0][lr+64] = w1.x; Bs[nb][lc+1][lr+64] = w1.y; Bs[nb][lc+2][lr+64] = w1.z; Bs[nb][lc+3][lr+64] = w1.w;
            __syncthreads();
            sb = nb;
        }
    }

    float bv[8];
#pragma unroll
    for (int j = 0; j < 8; j++) bv[j] = bias[bn + tx*8 + j];

#pragma unroll
    for (int i = 0; i < 8; i++) {
        int m  = bm + ty*8 + i;
        int n0 = bn + tx*8;
#pragma unroll
        for (int v = 0; v < 2; v++) {
            float4 o;
            o.x = acc[i][v*4+0] + bv[v*4+0];
            o.y = acc[i][v*4+1] + bv[v*4+1];
            o.z = acc[i][v*4+2] + bv[v*4+2];
            o.w = acc[i][v*4+3] + bv[v*4+3];
            int n = n0 + v*4;
            if (MODE == 0) {
                *(float4*)(C + (size_t)m * N + n) = o;
            } else {
                int b = m >> 11;
                int l = m & 2047;
                int h = n >> 6;
                int dk = n & 63;
                *(float4*)(C + ((((size_t)b*HH + h)*LL + l)*DKK) + dk) = o;
            }
        }
    }
}

// ---------------------------------------------------------------------------
// Causal flash attention, fp32, vectorized-smem version.
// One block = 64 queries of one (b,h). BQ=BKV=64, DK=64, 256 threads.
// Layouts: Qt[d][r], Kt[d][c] (transposed), Vs[k][c], Pt[k][r] (transposed).
// All mainloop smem reads are LDS.128. Softmax entirely in registers via
// 16-lane shfl reductions; m/l state register-resident (replicated per row).
// smem = 4 * 64 * 68 * 4B = 69632 B (dynamic).
// ---------------------------------------------------------------------------
#define APAD 68

__global__ __launch_bounds__(256)
void attn_kernel(const float* __restrict__ Qg, const float* __restrict__ Kg,
                 const float* __restrict__ Vg, float* __restrict__ Og)
{
    extern __shared__ float smbuf[];
    float (*Qt)[APAD] = (float(*)[APAD])(smbuf);
    float (*Kt)[APAD] = (float(*)[APAD])(smbuf + 64*APAD);
    float (*Vs)[APAD] = (float(*)[APAD])(smbuf + 2*64*APAD);
    float (*Pt)[APAD] = (float(*)[APAD])(smbuf + 3*64*APAD);

    const int tid = threadIdx.x;
    const int qt = gridDim.x - 1 - blockIdx.x;   // big tiles first
    const int h = blockIdx.y, b = blockIdx.z;
    const size_t base = ((size_t)b*HH + h) * LL * DKK;
    const float* Qp = Qg + base + (size_t)qt * 64 * DKK;
    const float* Kp = Kg + base;
    const float* Vp = Vg + base;

    // loader mapping: lane-major over rows -> conflict-free transpose STS
    const int lr = tid & 63;     // tile row (k or q index)
    const int dg = tid >> 6;     // d-group 0..3 (16 floats each)

    // Load Q tile transposed: Qt[d][r]
    {
        const float* src = Qp + lr*DKK + dg*16;
#pragma unroll
        for (int jj = 0; jj < 4; jj++) {
            float4 v = *(const float4*)(src + jj*4);
            int d = dg*16 + jj*4;
            Qt[d+0][lr] = v.x; Qt[d+1][lr] = v.y; Qt[d+2][lr] = v.z; Qt[d+3][lr] = v.w;
        }
    }

    const int tr = tid >> 4, tc = tid & 15;
    const int r0 = tr * 4, c0 = tc * 4;

    float O[4][4];
    float m_st[4], l_st[4];
#pragma unroll
    for (int i = 0; i < 4; i++) {
        m_st[i] = -1e30f; l_st[i] = 0.f;
#pragma unroll
        for (int j = 0; j < 4; j++) O[i][j] = 0.f;
    }

    const int q_lo = qt * 64;
    const float scale = 0.125f;   // 1/sqrt(64)

    for (int kt = 0; kt <= qt; kt++) {
        const float* Kpt = Kp + (size_t)kt * 64 * DKK;
        const float* Vpt = Vp + (size_t)kt * 64 * DKK;

        // prefetch K/V into regs (8 independent LDG.128 chains)
        float4 kr[4], vr[4];
        {
            const float* ks = Kpt + lr*DKK + dg*16;
            const float* vs = Vpt + lr*DKK + dg*16;
#pragma unroll
            for (int jj = 0; jj < 4; jj++) { kr[jj] = *(const float4*)(ks + jj*4); }
#pragma unroll
            for (int jj = 0; jj < 4; jj++) { vr[jj] = *(const float4*)(vs + jj*4); }
        }
        __syncthreads();   // prior iteration's PV reads done before overwrite
#pragma unroll
        for (int jj = 0; jj < 4; jj++) {
            int d = dg*16 + jj*4;
            Kt[d+0][lr] = kr[jj].x; Kt[d+1][lr] = kr[jj].y;
            Kt[d+2][lr] = kr[jj].z; Kt[d+3][lr] = kr[jj].w;
            *(float4*)&Vs[lr][dg*16 + jj*4] = vr[jj];
        }
        __syncthreads();

        // ---- S = Q K^T : 2 LDS.128 per 16 FMA ----
        float s[4][4];
#pragma unroll
        for (int i = 0; i < 4; i++)
#pragma unroll
            for (int j = 0; j < 4; j++) s[i][j] = 0.f;
#pragma unroll 4
        for (int d = 0; d < 64; d++) {
            float4 qa = *(const float4*)&Qt[d][r0];
            float4 ka = *(const float4*)&Kt[d][c0];
            s[0][0] = fmaf(qa.x, ka.x, s[0][0]); s[0][1] = fmaf(qa.x, ka.y, s[0][1]);
            s[0][2] = fmaf(qa.x, ka.z, s[0][2]); s[0][3] = fmaf(qa.x, ka.w, s[0][3]);
            s[1][0] = fmaf(qa.y, ka.x, s[1][0]); s[1][1] = fmaf(qa.y, ka.y, s[1][1]);
            s[1][2] = fmaf(qa.y, ka.z, s[1][2]); s[1][3] = fmaf(qa.y, ka.w, s[1][3]);
            s[2][0] = fmaf(qa.z, ka.x, s[2][0]); s[2][1] = fmaf(qa.z, ka.y, s[2][1]);
            s[2][2] = fmaf(qa.z, ka.z, s[2][2]); s[2][3] = fmaf(qa.z, ka.w, s[2][3]);
            s[3][0] = fmaf(qa.w, ka.x, s[3][0]); s[3][1] = fmaf(qa.w, ka.y, s[3][1]);
            s[3][2] = fmaf(qa.w, ka.z, s[3][2]); s[3][3] = fmaf(qa.w, ka.w, s[3][3]);
        }

        // scale (+ mask only on diagonal tile)
        if (kt == qt) {
#pragma unroll
            for (int i = 0; i < 4; i++) {
                int qi = r0 + i;         // local; ki local = c0+j
#pragma unroll
                for (int j = 0; j < 4; j++)
                    s[i][j] = (c0 + j <= qi) ? s[i][j]*scale : -1e30f;
            }
        } else {
#pragma unroll
            for (int i = 0; i < 4; i++)
#pragma unroll
                for (int j = 0; j < 4; j++) s[i][j] *= scale;
        }

        // ---- online softmax in registers (16-lane shfl over tc) ----
#pragma unroll
        for (int i = 0; i < 4; i++) {
            float mx = fmaxf(fmaxf(s[i][0], s[i][1]), fmaxf(s[i][2], s[i][3]));
            mx = fmaxf(mx, __shfl_xor_sync(0xffffffffu, mx, 1));
            mx = fmaxf(mx, __shfl_xor_sync(0xffffffffu, mx, 2));
            mx = fmaxf(mx, __shfl_xor_sync(0xffffffffu, mx, 4));
            mx = fmaxf(mx, __shfl_xor_sync(0xffffffffu, mx, 8));
            float mn = fmaxf(m_st[i], mx);
            float corr = __expf(m_st[i] - mn);
            m_st[i] = mn;
            float rs = 0.f;
#pragma unroll
            for (int j = 0; j < 4; j++) {
                s[i][j] = __expf(s[i][j] - mn);
                rs += s[i][j];
            }
            rs += __shfl_xor_sync(0xffffffffu, rs, 1);
            rs += __shfl_xor_sync(0xffffffffu, rs, 2);
            rs += __shfl_xor_sync(0xffffffffu, rs, 4);
            rs += __shfl_xor_sync(0xffffffffu, rs, 8);
            l_st[i] = l_st[i]*corr + rs;
#pragma unroll
            for (int j = 0; j < 4; j++) O[i][j] *= corr;
        }

        // write P transposed: Pt[k][r]
#pragma unroll
        for (int i = 0; i < 4; i++)
#pragma unroll
            for (int j = 0; j < 4; j++)
                Pt[c0+j][r0+i] = s[i][j];
        __syncthreads();

        // ---- O += P V : 2 LDS.128 per 16 FMA ----
#pragma unroll 4
        for (int k = 0; k < 64; k++) {
            float4 pv = *(const float4*)&Pt[k][r0];
            float4 vv = *(const float4*)&Vs[k][c0];
            O[0][0] = fmaf(pv.x, vv.x, O[0][0]); O[0][1] = fmaf(pv.x, vv.y, O[0][1]);
            O[0][2] = fmaf(pv.x, vv.z, O[0][2]); O[0][3] = fmaf(pv.x, vv.w, O[0][3]);
            O[1][0] = fmaf(pv.y, vv.x, O[1][0]); O[1][1] = fmaf(pv.y, vv.y, O[1][1]);
            O[1][2] = fmaf(pv.y, vv.z, O[1][2]); O[1][3] = fmaf(pv.y, vv.w, O[1][3]);
            O[2][0] = fmaf(pv.z, vv.x, O[2][0]); O[2][1] = fmaf(pv.z, vv.y, O[2][1]);
            O[2][2] = fmaf(pv.z, vv.z, O[2][2]); O[2][3] = fmaf(pv.z, vv.w, O[2][3]);
            O[3][0] = fmaf(pv.w, vv.x, O[3][0]); O[3][1] = fmaf(pv.w, vv.y, O[3][1]);
            O[3][2] = fmaf(pv.w, vv.z, O[3][2]); O[3][3] = fmaf(pv.w, vv.w, O[3][3]);
        }
    }

    // normalize + store merged-head [B, L, D]
#pragma unroll
    for (int i = 0; i < 4; i++) {
        float inv = 1.f / l_st[i];
        int q = q_lo + r0 + i;
        float4 o = make_float4(O[i][0]*inv, O[i][1]*inv, O[i][2]*inv, O[i][3]*inv);
        *(float4*)(Og + ((size_t)b*LL + q)*DD + h*DKK + c0) = o;
    }
}

// ---------------------------------------------------------------------------
extern "C" void kernel_launch(void* const* d_in, const int* in_sizes, int n_in,
                              void* d_out, int out_size)
{
    const float* query = (const float*)d_in[0];
    const float* key   = (const float*)d_in[1];
    const float* value = (const float*)d_in[2];
    // d_in[3] = mask: exactly triu(ones,k=1) causal -> applied analytically
    const float* Wq = (const float*)d_in[4];
    const float* bq = (const float*)d_in[5];
    const float* Wk = (const float*)d_in[6];
    const float* bk = (const float*)d_in[7];
    const float* Wv = (const float*)d_in[8];
    const float* bv = (const float*)d_in[9];
    const float* Wo = (const float*)d_in[10];
    const float* bo = (const float*)d_in[11];
    float* out = (float*)d_out;

    float *gQ, *gK, *gV, *gAo;
    cudaGetSymbolAddress((void**)&gQ,  g_Q);
    cudaGetSymbolAddress((void**)&gK,  g_K);
    cudaGetSymbolAddress((void**)&gV,  g_V);
    cudaGetSymbolAddress((void**)&gAo, g_Ao);

    const int smem_attn = 4*64*APAD*(int)sizeof(float);   // 69632 B
    cudaFuncSetAttribute(attn_kernel, cudaFuncAttributeMaxDynamicSharedMemorySize,
                         smem_attn);

    dim3 ggrid(8, 32);   // N/128, M/128
    gemm_kernel<1><<<ggrid, 256>>>(query, Wq, bq, gQ);
    gemm_kernel<1><<<ggrid, 256>>>(key,   Wk, bk, gK);
    gemm_kernel<1><<<ggrid, 256>>>(value, Wv, bv, gV);
    attn_kernel<<<dim3(LL/64, HH, BB), 256, smem_attn>>>(gQ, gK, gV, gAo);
    gemm_kernel<0><<<ggrid, 256>>>(gAo, Wo, bo, out);
}